// round 1
// baseline (speedup 1.0000x reference)
#include <cuda_runtime.h>
#include <stdint.h>

// PatchShift: out[b,t,h,w,c] = x[b, (t - S[h%3, w%3]) % T, h, w, c]
// Shapes: B=32, T=8, H=14, W=14, C=768 (fp32).
// Pure permutation along T, rows of C=768 floats stay contiguous.

#define B_ 32
#define T_ 8
#define H_ 14
#define W_ 14
#define C4_ 192   // 768 floats = 192 float4

__global__ __launch_bounds__(C4_) void patch_shift_kernel(
    const float4* __restrict__ x, float4* __restrict__ out)
{
    // blockIdx.x = h*14 + w  (0..195), blockIdx.y = t (0..7), blockIdx.z = b (0..31)
    const int hw = blockIdx.x;
    const int w  = hw % 14;        // compile-time-constant divisor -> mul/shift
    const int h  = hw / 14;
    const int t  = blockIdx.y;
    const int b  = blockIdx.z;

    // shift_table[h%3][w%3]
    const int Stab[9] = {-4, 1, 2, -1, 0, 3, -2, -3, 4};
    const int s  = Stab[(h % 3) * 3 + (w % 3)];
    const int ts = (t - s + 8) & 7;   // (t - S) mod 8, always non-negative input

    const long long row_out = ((((long long)b * T_ + t ) * H_ + h) * W_ + w) * C4_;
    const long long row_in  = ((((long long)b * T_ + ts) * H_ + h) * W_ + w) * C4_;

    out[row_out + threadIdx.x] = x[row_in + threadIdx.x];
}

extern "C" void kernel_launch(void* const* d_in, const int* in_sizes, int n_in,
                              void* d_out, int out_size)
{
    const float4* x   = (const float4*)d_in[0];
    float4*       out = (float4*)d_out;

    dim3 grid(H_ * W_, T_, B_);   // (196, 8, 32)
    patch_shift_kernel<<<grid, C4_>>>(x, out);
}

// round 2
// speedup vs baseline: 1.0131x; 1.0131x over previous
#include <cuda_runtime.h>
#include <stdint.h>

// PatchShift: out[b,t,h,w,c] = x[b, (t - S[h%3, w%3]) % 8, h, w, c]
// Shapes: B=32, T=8, H=14, W=14, C=768 (fp32) -> rows of 192 float4.
// One CTA per (b,h,w); each thread copies its channel float4 across all T=8
// slices with 8 batched independent loads (MLP=8), then 8 stores.

#define B_ 32
#define T_ 8
#define H_ 14
#define W_ 14
#define C4_ 192                         // 768 floats = 192 float4
#define TSTRIDE (H_ * W_ * C4_)         // float4 stride between time slices = 37632

__global__ __launch_bounds__(C4_) void patch_shift_kernel(
    const float4* __restrict__ x, float4* __restrict__ out)
{
    // blockIdx.x = h*14 + w (0..195), blockIdx.y = b (0..31)
    const int hw = blockIdx.x;
    const int w  = hw % 14;             // constant divisor -> mul/shift
    const int h  = hw / 14;
    const int b  = blockIdx.y;

    const int Stab[9] = {-4, 1, 2, -1, 0, 3, -2, -3, 4};
    const int s = Stab[(h % 3) * 3 + (w % 3)];

    // base index of (b, t=0, h, w, c4=tid)
    const long long base = ((long long)b * T_ * H_ * W_ + hw) * C4_ + threadIdx.x;

    float4 v[T_];
    #pragma unroll
    for (int t = 0; t < T_; ++t) {
        const int ts = (t - s + 8) & 7;          // source time slice
        v[t] = x[base + (long long)ts * TSTRIDE];
    }
    #pragma unroll
    for (int t = 0; t < T_; ++t) {
        out[base + (long long)t * TSTRIDE] = v[t];
    }
}

extern "C" void kernel_launch(void* const* d_in, const int* in_sizes, int n_in,
                              void* d_out, int out_size)
{
    const float4* x   = (const float4*)d_in[0];
    float4*       out = (float4*)d_out;

    dim3 grid(H_ * W_, B_);             // (196, 32) = 6272 CTAs
    patch_shift_kernel<<<grid, C4_>>>(x, out);
}

// round 3
// speedup vs baseline: 1.0451x; 1.0316x over previous
#include <cuda_runtime.h>
#include <stdint.h>

// PatchShift: out[b,t,h,w,c] = x[b, (t - S[h%3, w%3]) % 8, h, w, c]
// Shapes: B=32, T=8, H=14, W=14, C=768 (fp32) -> rows of 192 float4.
// One CTA per (b, hw-pair): 384 threads = 2 pixels x 192 channel-float4s.
// Each thread copies its float4 across all T=8 slices: 8 batched streaming
// loads (MLP=8) then 8 streaming stores. No reuse -> evict-first hints.

#define B_ 32
#define T_ 8
#define H_ 14
#define W_ 14
#define C4_ 192                         // 768 floats = 192 float4
#define TSTRIDE (H_ * W_ * C4_)         // float4 stride between time slices = 37632

__global__ __launch_bounds__(2 * C4_) void patch_shift_kernel(
    const float4* __restrict__ x, float4* __restrict__ out)
{
    // blockIdx.x = pixel-pair index (0..97), blockIdx.y = b (0..31)
    const int hw = blockIdx.x * 2 + (threadIdx.x >= C4_ ? 1 : 0);  // 0..195
    const int c4 = threadIdx.x - (threadIdx.x >= C4_ ? C4_ : 0);   // 0..191
    const int w  = hw % 14;             // constant divisor -> mul/shift
    const int h  = hw / 14;
    const int b  = blockIdx.y;

    const int Stab[9] = {-4, 1, 2, -1, 0, 3, -2, -3, 4};
    const int s = Stab[(h % 3) * 3 + (w % 3)];

    // base index of (b, t=0, h, w, c4)
    const long long base = ((long long)b * T_ * H_ * W_ + hw) * C4_ + c4;

    float4 v[T_];
    #pragma unroll
    for (int t = 0; t < T_; ++t) {
        const int ts = (t - s + 8) & 7;              // source time slice
        v[t] = __ldcs(&x[base + (long long)ts * TSTRIDE]);
    }
    #pragma unroll
    for (int t = 0; t < T_; ++t) {
        __stcs(&out[base + (long long)t * TSTRIDE], v[t]);
    }
}

extern "C" void kernel_launch(void* const* d_in, const int* in_sizes, int n_in,
                              void* d_out, int out_size)
{
    const float4* x   = (const float4*)d_in[0];
    float4*       out = (float4*)d_out;

    dim3 grid((H_ * W_) / 2, B_);       // (98, 32) = 3136 CTAs, 384 thr each
    patch_shift_kernel<<<grid, 2 * C4_>>>(x, out);
}